// round 2
// baseline (speedup 1.0000x reference)
#include <cuda_runtime.h>

#define DMODEL 2048
#define NH     16
#define DKH    128
#define SEQ    2048
#define BATCH  4

// Scratch (alloc-free rule: __device__ globals). 4 x 64MB.
__device__ float g_q[(size_t)BATCH * NH * SEQ * DKH];
__device__ float g_k[(size_t)BATCH * NH * SEQ * DKH];
__device__ float g_v[(size_t)BATCH * NH * SEQ * DKH];
__device__ float g_attn[(size_t)BATCH * SEQ * DMODEL];

// ---------------------------------------------------------------------------
// C[m,n] = sum_k A[m,k] * B[n,k]   (A: MxK row-major, B: NxK row-major)
// HEADS=1: write C in [B*H][S][DKH] layout (for Q/K/V). HEADS=0: plain MxN.
// BM=BN=128, BK=8, 256 threads, 8x8 per-thread microtile.
// ---------------------------------------------------------------------------
template <int HEADS>
__global__ __launch_bounds__(256) void gemm_nt(const float* __restrict__ A,
                                               const float* __restrict__ B,
                                               float* __restrict__ C,
                                               int M, int N, int K) {
    __shared__ float As[8][132];  // pad 4 -> conflict-free transposed stores + aligned frags
    __shared__ float Bs[8][132];

    const int tid = threadIdx.x;
    const int tx  = tid & 15;     // col group
    const int ty  = tid >> 4;     // row group
    const int rowBlock = blockIdx.y << 7;
    const int colBlock = blockIdx.x << 7;

    const int lr = tid >> 1;        // 0..127: tile row to load
    const int lc = (tid & 1) << 2;  // 0 or 4: k offset

    const float* Ap = A + (size_t)(rowBlock + lr) * K + lc;
    const float* Bp = B + (size_t)(colBlock + lr) * K + lc;

    float acc[8][8];
#pragma unroll
    for (int i = 0; i < 8; i++)
#pragma unroll
        for (int j = 0; j < 8; j++) acc[i][j] = 0.0f;

    for (int k0 = 0; k0 < K; k0 += 8) {
        float4 a4 = *(const float4*)(Ap + k0);
        float4 b4 = *(const float4*)(Bp + k0);
        As[lc + 0][lr] = a4.x; As[lc + 1][lr] = a4.y;
        As[lc + 2][lr] = a4.z; As[lc + 3][lr] = a4.w;
        Bs[lc + 0][lr] = b4.x; Bs[lc + 1][lr] = b4.y;
        Bs[lc + 2][lr] = b4.z; Bs[lc + 3][lr] = b4.w;
        __syncthreads();

#pragma unroll
        for (int k = 0; k < 8; k++) {
            float af[8], bf[8];
            *(float4*)&af[0] = *(const float4*)&As[k][ty * 8];
            *(float4*)&af[4] = *(const float4*)&As[k][ty * 8 + 4];
            *(float4*)&bf[0] = *(const float4*)&Bs[k][tx * 8];
            *(float4*)&bf[4] = *(const float4*)&Bs[k][tx * 8 + 4];
#pragma unroll
            for (int i = 0; i < 8; i++)
#pragma unroll
                for (int j = 0; j < 8; j++) acc[i][j] += af[i] * bf[j];
        }
        __syncthreads();
    }

    if (HEADS) {
        // m = b*SEQ + s ; n = h*DKH + dk -> out[((b*NH+h)*SEQ + s)*DKH + dk]
#pragma unroll
        for (int i = 0; i < 8; i++) {
            const int m = rowBlock + ty * 8 + i;
            const int b = m >> 11;         // /SEQ
            const int s = m & (SEQ - 1);
            const int n0 = colBlock + tx * 8;
            const int h  = n0 >> 7;        // 8 contiguous cols stay in one head
            const int dk = n0 & 127;
            float* dst = C + (size_t)((b * NH + h) * SEQ + s) * DKH + dk;
            *(float4*)&dst[0] = *(float4*)&acc[i][0];
            *(float4*)&dst[4] = *(float4*)&acc[i][4];
        }
    } else {
#pragma unroll
        for (int i = 0; i < 8; i++) {
            const int m = rowBlock + ty * 8 + i;
            float* dst = C + (size_t)m * N + colBlock + tx * 8;
            *(float4*)&dst[0] = *(float4*)&acc[i][0];
            *(float4*)&dst[4] = *(float4*)&acc[i][4];
        }
    }
}

// ---------------------------------------------------------------------------
// Flash attention (fp32, online softmax, causal optional).
// Grid: (SEQ/64, BATCH*NH). Block: 256 threads (16x16).
// Thread (ty,tx): scores rows ty*4..+3, cols tx*4..+3 ; O rows ty*4..+3, cols tx*8..+7.
// ---------------------------------------------------------------------------
#define QK_STRIDE 68    // d-major Q/K tiles: [128][64+4]
#define V_STRIDE  132   // row-major V tile:  [64][128+4]
#define SMEM_FLOATS (2 * 128 * QK_STRIDE + 64 * V_STRIDE + 64 * QK_STRIDE)

__global__ __launch_bounds__(256) void flash_attn(const int* __restrict__ use_mask_p) {
    extern __shared__ float sm[];
    float* QsT = sm;                                  // [128][68]
    float* KsT = sm + 128 * QK_STRIDE;                // [128][68]
    float* Vs  = sm + 2 * 128 * QK_STRIDE;            // [64][132]
    float* Ps  = sm + 2 * 128 * QK_STRIDE + 64 * V_STRIDE;  // [64][68]

    const int tid = threadIdx.x;
    const int tx  = tid & 15;
    const int ty  = tid >> 4;
    const int bh    = blockIdx.y;
    const int qbase = blockIdx.x << 6;

    const float* Qg = g_q + (size_t)bh * SEQ * DKH;
    const float* Kg = g_k + (size_t)bh * SEQ * DKH;
    const float* Vg = g_v + (size_t)bh * SEQ * DKH;

    // Load Q tile transposed: 64 rows x 128 d
#pragma unroll
    for (int p = 0; p < 8; p++) {
        const int idx = p * 256 + tid;      // 0..2047 float4 slots
        const int r   = idx >> 5;           // 0..63
        const int d4  = (idx & 31) << 2;    // 0..124
        float4 q4 = *(const float4*)(Qg + (size_t)(qbase + r) * DKH + d4);
        QsT[(d4 + 0) * QK_STRIDE + r] = q4.x;
        QsT[(d4 + 1) * QK_STRIDE + r] = q4.y;
        QsT[(d4 + 2) * QK_STRIDE + r] = q4.z;
        QsT[(d4 + 3) * QK_STRIDE + r] = q4.w;
    }

    float m_i[4], l_i[4], o[4][8];
#pragma unroll
    for (int i = 0; i < 4; i++) {
        m_i[i] = -1e30f;
        l_i[i] = 0.0f;
#pragma unroll
        for (int c = 0; c < 8; c++) o[i][c] = 0.0f;
    }

    const int mask = *use_mask_p;
    const int nt   = mask ? (blockIdx.x + 1) : (SEQ >> 6);

    for (int t = 0; t < nt; t++) {
        const int kb = t << 6;
        __syncthreads();  // previous iter done reading KsT/Vs/Ps; QsT writes visible
#pragma unroll
        for (int p = 0; p < 8; p++) {
            const int idx = p * 256 + tid;
            const int r   = idx >> 5;
            const int d4  = (idx & 31) << 2;
            float4 k4 = *(const float4*)(Kg + (size_t)(kb + r) * DKH + d4);
            KsT[(d4 + 0) * QK_STRIDE + r] = k4.x;
            KsT[(d4 + 1) * QK_STRIDE + r] = k4.y;
            KsT[(d4 + 2) * QK_STRIDE + r] = k4.z;
            KsT[(d4 + 3) * QK_STRIDE + r] = k4.w;
            float4 v4 = *(const float4*)(Vg + (size_t)(kb + r) * DKH + d4);
            *(float4*)&Vs[r * V_STRIDE + d4] = v4;  // 528B row stride: 16B aligned
        }
        __syncthreads();

        // S = Q K^T / sqrt(dk)
        float s[4][4];
#pragma unroll
        for (int i = 0; i < 4; i++)
#pragma unroll
            for (int j = 0; j < 4; j++) s[i][j] = 0.0f;

#pragma unroll 4
        for (int d = 0; d < 128; d++) {
            float4 qf = *(const float4*)&QsT[d * QK_STRIDE + ty * 4];
            float4 kf = *(const float4*)&KsT[d * QK_STRIDE + tx * 4];
            const float qa[4] = {qf.x, qf.y, qf.z, qf.w};
            const float ka[4] = {kf.x, kf.y, kf.z, kf.w};
#pragma unroll
            for (int i = 0; i < 4; i++)
#pragma unroll
                for (int j = 0; j < 4; j++) s[i][j] += qa[i] * ka[j];
        }

        const float sc = 0.08838834764831845f;  // 1/sqrt(128)
        float mt[4];
#pragma unroll
        for (int i = 0; i < 4; i++) {
            float mm = -1e30f;
#pragma unroll
            for (int j = 0; j < 4; j++) {
                s[i][j] *= sc;
                if (mask && (kb + tx * 4 + j) > (qbase + ty * 4 + i)) s[i][j] = -1e30f;
                mm = fmaxf(mm, s[i][j]);
            }
            mt[i] = mm;
        }
        // row max across the 16 tx lanes (lanes [0..15]/[16..31] are tx groups)
#pragma unroll
        for (int off = 8; off; off >>= 1)
#pragma unroll
            for (int i = 0; i < 4; i++)
                mt[i] = fmaxf(mt[i], __shfl_xor_sync(0xffffffffu, mt[i], off, 16));

        float rs[4];
#pragma unroll
        for (int i = 0; i < 4; i++) {
            const float mn    = fmaxf(m_i[i], mt[i]);
            const float alpha = __expf(m_i[i] - mn);
            m_i[i] = mn;
            float sum = 0.0f;
#pragma unroll
            for (int j = 0; j < 4; j++) {
                const float pv = __expf(s[i][j] - mn);
                s[i][j] = pv;
                sum += pv;
            }
            rs[i]  = sum;
            l_i[i] *= alpha;
#pragma unroll
            for (int c = 0; c < 8; c++) o[i][c] *= alpha;
        }
#pragma unroll
        for (int off = 8; off; off >>= 1)
#pragma unroll
            for (int i = 0; i < 4; i++)
                rs[i] += __shfl_xor_sync(0xffffffffu, rs[i], off, 16);
#pragma unroll
        for (int i = 0; i < 4; i++) l_i[i] += rs[i];

        // Stage P through smem so every thread sees full rows for P@V
#pragma unroll
        for (int i = 0; i < 4; i++)
#pragma unroll
            for (int j = 0; j < 4; j++)
                Ps[(ty * 4 + i) * QK_STRIDE + tx * 4 + j] = s[i][j];
        __syncthreads();

        // O += P @ V
#pragma unroll 4
        for (int j = 0; j < 64; j++) {
            float4 v0 = *(const float4*)&Vs[j * V_STRIDE + tx * 8];
            float4 v1 = *(const float4*)&Vs[j * V_STRIDE + tx * 8 + 4];
            const float vv[8] = {v0.x, v0.y, v0.z, v0.w, v1.x, v1.y, v1.z, v1.w};
#pragma unroll
            for (int i = 0; i < 4; i++) {
                const float pf = Ps[(ty * 4 + i) * QK_STRIDE + j];
#pragma unroll
                for (int c = 0; c < 8; c++) o[i][c] += pf * vv[c];
            }
        }
    }

    // Normalize and write to [B, S, H*DKH] for the output projection
    const int b = bh >> 4;
    const int h = bh & 15;
#pragma unroll
    for (int i = 0; i < 4; i++) {
        const float inv  = 1.0f / l_i[i];
        const int   srow = qbase + ty * 4 + i;
        float* dst = g_attn + (size_t)(b * SEQ + srow) * DMODEL + h * DKH + tx * 8;
        float r0[4], r1[4];
#pragma unroll
        for (int c = 0; c < 4; c++) { r0[c] = o[i][c] * inv; r1[c] = o[i][c + 4] * inv; }
        *(float4*)&dst[0] = *(float4*)r0;
        *(float4*)&dst[4] = *(float4*)r1;
    }
}

// ---------------------------------------------------------------------------
extern "C" void kernel_launch(void* const* d_in, const int* in_sizes, int n_in,
                              void* d_out, int out_size) {
    const float* x  = (const float*)d_in[0];
    const float* Wq = (const float*)d_in[1];
    const float* Wk = (const float*)d_in[2];
    const float* Wv = (const float*)d_in[3];
    const float* Wo = (const float*)d_in[4];
    const int* use_mask = (const int*)d_in[5];  // low 32 bits of flag: works for i32/i64

    float *q, *k, *v, *attn;
    cudaGetSymbolAddress((void**)&q, g_q);
    cudaGetSymbolAddress((void**)&k, g_k);
    cudaGetSymbolAddress((void**)&v, g_v);
    cudaGetSymbolAddress((void**)&attn, g_attn);

    const int smem_bytes = SMEM_FLOATS * (int)sizeof(float);  // ~121 KB
    cudaFuncSetAttribute(flash_attn, cudaFuncAttributeMaxDynamicSharedMemorySize, smem_bytes);

    const int M = BATCH * SEQ;  // 8192
    dim3 gblk(256);
    dim3 ggrd(DMODEL / 128, M / 128);  // (16, 64)

    gemm_nt<1><<<ggrd, gblk>>>(x, Wq, q, M, DMODEL, DMODEL);
    gemm_nt<1><<<ggrd, gblk>>>(x, Wk, k, M, DMODEL, DMODEL);
    gemm_nt<1><<<ggrd, gblk>>>(x, Wv, v, M, DMODEL, DMODEL);

    flash_attn<<<dim3(SEQ / 64, BATCH * NH), 256, smem_bytes>>>(use_mask);

    gemm_nt<0><<<ggrd, gblk>>>(attn, Wo, (float*)d_out, M, DMODEL, DMODEL);
}

// round 9
// speedup vs baseline: 2.0026x; 2.0026x over previous
#include <cuda_runtime.h>
#include <cuda_bf16.h>
#include <cstdint>

#define DMODEL 2048
#define NH     16
#define DKH    128
#define SEQ    2048
#define BATCH  4
#define MROWS  (BATCH * SEQ)   /* 8192 */
#define GK     DMODEL          /* GEMM K */

// ---------------- scratch (__device__ globals per alloc-free rule) ----------
__device__ float g_q[(size_t)BATCH * NH * SEQ * DKH];
__device__ float g_k[(size_t)BATCH * NH * SEQ * DKH];
__device__ float g_v[(size_t)BATCH * NH * SEQ * DKH];
__device__ float g_attn[(size_t)BATCH * SEQ * DMODEL];
__device__ __nv_bfloat16 g_xh[(size_t)MROWS * DMODEL];
__device__ __nv_bfloat16 g_xl[(size_t)MROWS * DMODEL];
__device__ __nv_bfloat16 g_wh[(size_t)DMODEL * DMODEL];
__device__ __nv_bfloat16 g_wl[(size_t)DMODEL * DMODEL];

// ---------------- helpers (base-ISA only: ldmatrix / mma.sync / cp.async) ---
__device__ __forceinline__ uint32_t smem_u32(const void* p) {
    uint32_t a;
    asm("{ .reg .u64 t; cvta.to.shared.u64 t, %1; cvt.u32.u64 %0, t; }" : "=r"(a) : "l"(p));
    return a;
}
__device__ __forceinline__ void ldm4(uint32_t* r, uint32_t addr) {
    asm volatile("ldmatrix.sync.aligned.m8n8.x4.shared.b16 {%0,%1,%2,%3}, [%4];"
                 : "=r"(r[0]), "=r"(r[1]), "=r"(r[2]), "=r"(r[3]) : "r"(addr));
}
__device__ __forceinline__ void mma16816(float* d, const uint32_t* a, const uint32_t* b) {
    asm volatile(
        "mma.sync.aligned.m16n8k16.row.col.f32.bf16.bf16.f32 "
        "{%0,%1,%2,%3}, {%4,%5,%6,%7}, {%8,%9}, {%0,%1,%2,%3};"
        : "+f"(d[0]), "+f"(d[1]), "+f"(d[2]), "+f"(d[3])
        : "r"(a[0]), "r"(a[1]), "r"(a[2]), "r"(a[3]), "r"(b[0]), "r"(b[1]));
}
__device__ __forceinline__ void cp16(uint32_t sa, const void* ga) {
    asm volatile("cp.async.cg.shared.global [%0], [%1], 16;" :: "r"(sa), "l"(ga));
}

// ---------------- fp32 -> bf16 hi/lo split ---------------------------------
__global__ __launch_bounds__(256) void split_kernel(const float* __restrict__ src,
                                                    __nv_bfloat16* __restrict__ hi,
                                                    __nv_bfloat16* __restrict__ lo,
                                                    int n4) {
    const int i = blockIdx.x * blockDim.x + threadIdx.x;
    if (i >= n4) return;
    const float4 v = ((const float4*)src)[i];
    __nv_bfloat16 hb[4], lb[4];
    const float a[4] = {v.x, v.y, v.z, v.w};
#pragma unroll
    for (int j = 0; j < 4; j++) {
        const __nv_bfloat16 h = __float2bfloat16(a[j]);
        hb[j] = h;
        lb[j] = __float2bfloat16(a[j] - __bfloat162float(h));
    }
    ((uint2*)hi)[i] = *(const uint2*)hb;
    ((uint2*)lo)[i] = *(const uint2*)lb;
}

// ---------------- HMMA split-bf16 GEMM --------------------------------------
// C[m,n] = sum_k A[m,k]*B[n,k]  (NT). CTA 128x128, BK=32, 256 thr.
// Warp grid 2(m)x4(n): warp tile 64x32 = 4x4 m16n8k16 atoms.
// 3 terms: Ah*Bh + Ah*Bl + Al*Bh accumulate into fp32 regs.
// smem per stage: Ah|Al|Bh|Bl, each 128x32 bf16 (8KB) with XOR swizzle
//   off16(r, g) = r*4 + (g ^ ((r>>1)&3))   [16B granules] -> conflict-free ldmatrix.
#define BK        32
#define NSTAGE    (GK / BK)   /* 64 */
#define TILE_OFF  8192
#define STAGE_B   32768
#define GEMM_SMEM (2 * STAGE_B)  /* 64 KB */

template <int HEADS>
__global__ __launch_bounds__(256) void gemm_mma(const __nv_bfloat16* __restrict__ Ah,
                                                const __nv_bfloat16* __restrict__ Al,
                                                const __nv_bfloat16* __restrict__ Bh,
                                                const __nv_bfloat16* __restrict__ Bl,
                                                float* __restrict__ C) {
    extern __shared__ char smb[];
    const uint32_t sb32 = smem_u32(smb);

    const int tid  = threadIdx.x;
    const int lane = tid & 31;
    const int wid  = tid >> 5;
    const int wm   = wid & 1;   // 0..1 -> 64 rows
    const int wn   = wid >> 1;  // 0..3 -> 32 cols
    const int rowBlock = blockIdx.y << 7;
    const int colBlock = blockIdx.x << 7;

    const __nv_bfloat16* tp[4] = {Ah + (size_t)rowBlock * GK, Al + (size_t)rowBlock * GK,
                                  Bh + (size_t)colBlock * GK, Bl + (size_t)colBlock * GK};

    // per-thread load slots: t=0..7 -> tile t>>1, row (t&1)*64 + tid/4, granule tid&3
    const int lr = tid >> 2;      // 0..63
    const int lcg = tid & 3;      // granule 0..3 (8 bf16 = 16B)

    float acc[4][4][4];
#pragma unroll
    for (int i = 0; i < 4; i++)
#pragma unroll
        for (int j = 0; j < 4; j++)
#pragma unroll
            for (int e = 0; e < 4; e++) acc[i][j][e] = 0.0f;

    // ---- stage loader ----
    auto load_stage = [&](int s) {
        const int kc = s * BK;
        const uint32_t sbase = sb32 + (uint32_t)(s & 1) * STAGE_B;
#pragma unroll
        for (int t = 0; t < 8; t++) {
            const int tile = t >> 1;
            const int r    = ((t & 1) << 6) + lr;
            const uint32_t off = (uint32_t)(((r << 2) + (lcg ^ ((r >> 1) & 3))) << 4);
            cp16(sbase + tile * TILE_OFF + off,
                 tp[tile] + (size_t)r * GK + kc + (lcg << 3));
        }
        asm volatile("cp.async.commit_group;");
    };

    load_stage(0);
    load_stage(1);

    for (int s = 0; s < NSTAGE; s++) {
        if (s < NSTAGE - 2)
            asm volatile("cp.async.wait_group 1;");
        else
            asm volatile("cp.async.wait_group 0;");
        __syncthreads();

        const uint32_t sbase = sb32 + (uint32_t)(s & 1) * STAGE_B;
#pragma unroll
        for (int k16 = 0; k16 < 2; k16++) {
            uint32_t fah[4][4], fal[4][4], fbh[4][2], fbl[4][2];
            // A fragments (Ah, Al): rows wm*64 + am*16 + lane%16, granule k16*2 + lane/16
            const int ar0 = (wm << 6) + (lane & 15);
            const int ag  = (k16 << 1) + (lane >> 4);
#pragma unroll
            for (int am = 0; am < 4; am++) {
                const int r = ar0 + (am << 4);
                const uint32_t off = (uint32_t)(((r << 2) + (ag ^ ((r >> 1) & 3))) << 4);
                ldm4(fah[am], sbase + 0 * TILE_OFF + off);
                ldm4(fal[am], sbase + 1 * TILE_OFF + off);
            }
            // B fragments (Bh, Bl): pair p covers n-atoms 2p,2p+1
            const int br0 = (wn << 5) + ((lane >> 4) << 3) + (lane & 7);
            const int bg  = (k16 << 1) + ((lane >> 3) & 1);
#pragma unroll
            for (int p = 0; p < 2; p++) {
                const int r = br0 + (p << 4);
                const uint32_t off = (uint32_t)(((r << 2) + (bg ^ ((r >> 1) & 3))) << 4);
                uint32_t q[4];
                ldm4(q, sbase + 2 * TILE_OFF + off);
                fbh[p * 2][0] = q[0]; fbh[p * 2][1] = q[1];
                fbh[p * 2 + 1][0] = q[2]; fbh[p * 2 + 1][1] = q[3];
                ldm4(q, sbase + 3 * TILE_OFF + off);
                fbl[p * 2][0] = q[0]; fbl[p * 2][1] = q[1];
                fbl[p * 2 + 1][0] = q[2]; fbl[p * 2 + 1][1] = q[3];
            }
#pragma unroll
            for (int am = 0; am < 4; am++)
#pragma unroll
                for (int an = 0; an < 4; an++) {
                    mma16816(acc[am][an], fah[am], fbh[an]);
                    mma16816(acc[am][an], fah[am], fbl[an]);
                    mma16816(acc[am][an], fal[am], fbh[an]);
                }
        }
        __syncthreads();
        if (s + 2 < NSTAGE) load_stage(s + 2);
    }

    // ---- epilogue ----
    const int gr = lane >> 2;          // row in atom
    const int tc = (lane & 3) << 1;    // col pair in atom
#pragma unroll
    for (int am = 0; am < 4; am++) {
#pragma unroll
        for (int an = 0; an < 4; an++) {
            const int colL = (wn << 5) + (an << 3) + tc;
#pragma unroll
            for (int half = 0; half < 2; half++) {
                const int m = rowBlock + (wm << 6) + (am << 4) + gr + (half << 3);
                float* dst;
                if (HEADS) {
                    const int b = m >> 11;
                    const int ss = m & (SEQ - 1);
                    dst = C + (size_t)((b * NH + blockIdx.x) * SEQ + ss) * DKH + colL;
                } else {
                    dst = C + (size_t)m * DMODEL + colBlock + colL;
                }
                float2 v = make_float2(acc[am][an][half * 2], acc[am][an][half * 2 + 1]);
                *(float2*)dst = v;
            }
        }
    }
}

// ---------------- flash attention (fp32, unchanged from R2 pass) -----------
#define QK_STRIDE 68
#define V_STRIDE  132
#define SMEM_FLOATS (2 * 128 * QK_STRIDE + 64 * V_STRIDE + 64 * QK_STRIDE)

__global__ __launch_bounds__(256) void flash_attn(const int* __restrict__ use_mask_p) {
    extern __shared__ float sm[];
    float* QsT = sm;
    float* KsT = sm + 128 * QK_STRIDE;
    float* Vs  = sm + 2 * 128 * QK_STRIDE;
    float* Ps  = sm + 2 * 128 * QK_STRIDE + 64 * V_STRIDE;

    const int tid = threadIdx.x;
    const int tx  = tid & 15;
    const int ty  = tid >> 4;
    const int bh    = blockIdx.y;
    const int qbase = blockIdx.x << 6;

    const float* Qg = g_q + (size_t)bh * SEQ * DKH;
    const float* Kg = g_k + (size_t)bh * SEQ * DKH;
    const float* Vg = g_v + (size_t)bh * SEQ * DKH;

#pragma unroll
    for (int p = 0; p < 8; p++) {
        const int idx = p * 256 + tid;
        const int r   = idx >> 5;
        const int d4  = (idx & 31) << 2;
        float4 q4 = *(const float4*)(Qg + (size_t)(qbase + r) * DKH + d4);
        QsT[(d4 + 0) * QK_STRIDE + r] = q4.x;
        QsT[(d4 + 1) * QK_STRIDE + r] = q4.y;
        QsT[(d4 + 2) * QK_STRIDE + r] = q4.z;
        QsT[(d4 + 3) * QK_STRIDE + r] = q4.w;
    }

    float m_i[4], l_i[4], o[4][8];
#pragma unroll
    for (int i = 0; i < 4; i++) {
        m_i[i] = -1e30f;
        l_i[i] = 0.0f;
#pragma unroll
        for (int c = 0; c < 8; c++) o[i][c] = 0.0f;
    }

    const int mask = *use_mask_p;
    const int nt   = mask ? (blockIdx.x + 1) : (SEQ >> 6);

    for (int t = 0; t < nt; t++) {
        const int kb = t << 6;
        __syncthreads();
#pragma unroll
        for (int p = 0; p < 8; p++) {
            const int idx = p * 256 + tid;
            const int r   = idx >> 5;
            const int d4  = (idx & 31) << 2;
            float4 k4 = *(const float4*)(Kg + (size_t)(kb + r) * DKH + d4);
            KsT[(d4 + 0) * QK_STRIDE + r] = k4.x;
            KsT[(d4 + 1) * QK_STRIDE + r] = k4.y;
            KsT[(d4 + 2) * QK_STRIDE + r] = k4.z;
            KsT[(d4 + 3) * QK_STRIDE + r] = k4.w;
            float4 v4 = *(const float4*)(Vg + (size_t)(kb + r) * DKH + d4);
            *(float4*)&Vs[r * V_STRIDE + d4] = v4;
        }
        __syncthreads();

        float s[4][4];
#pragma unroll
        for (int i = 0; i < 4; i++)
#pragma unroll
            for (int j = 0; j < 4; j++) s[i][j] = 0.0f;

#pragma unroll 4
        for (int d = 0; d < 128; d++) {
            float4 qf = *(const float4*)&QsT[d * QK_STRIDE + ty * 4];
            float4 kf = *(const float4*)&KsT[d * QK_STRIDE + tx * 4];
            const float qa[4] = {qf.x, qf.y, qf.z, qf.w};
            const float ka[4] = {kf.x, kf.y, kf.z, kf.w};
#pragma unroll
            for (int i = 0; i < 4; i++)
#pragma unroll
                for (int j = 0; j < 4; j++) s[i][j] += qa[i] * ka[j];
        }

        const float sc = 0.08838834764831845f;
        float mt[4];
#pragma unroll
        for (int i = 0; i < 4; i++) {
            float mm = -1e30f;
#pragma unroll
            for (int j = 0; j < 4; j++) {
                s[i][j] *= sc;
                if (mask && (kb + tx * 4 + j) > (qbase + ty * 4 + i)) s[i][j] = -1e30f;
                mm = fmaxf(mm, s[i][j]);
            }
            mt[i] = mm;
        }
#pragma unroll
        for (int off = 8; off; off >>= 1)
#pragma unroll
            for (int i = 0; i < 4; i++)
                mt[i] = fmaxf(mt[i], __shfl_xor_sync(0xffffffffu, mt[i], off, 16));

        float rs[4];
#pragma unroll
        for (int i = 0; i < 4; i++) {
            const float mn    = fmaxf(m_i[i], mt[i]);
            const float alpha = __expf(m_i[i] - mn);
            m_i[i] = mn;
            float sum = 0.0f;
#pragma unroll
            for (int j = 0; j < 4; j++) {
                const float pv = __expf(s[i][j] - mn);
                s[i][j] = pv;
                sum += pv;
            }
            rs[i]  = sum;
            l_i[i] *= alpha;
#pragma unroll
            for (int c = 0; c < 8; c++) o[i][c] *= alpha;
        }
#pragma unroll
        for (int off = 8; off; off >>= 1)
#pragma unroll
            for (int i = 0; i < 4; i++)
                rs[i] += __shfl_xor_sync(0xffffffffu, rs[i], off, 16);
#pragma unroll
        for (int i = 0; i < 4; i++) l_i[i] += rs[i];

#pragma unroll
        for (int i = 0; i < 4; i++)
#pragma unroll
            for (int j = 0; j < 4; j++)
                Ps[(ty * 4 + i) * QK_STRIDE + tx * 4 + j] = s[i][j];
        __syncthreads();

#pragma unroll 4
        for (int j = 0; j < 64; j++) {
            float4 v0 = *(const float4*)&Vs[j * V_STRIDE + tx * 8];
            float4 v1 = *(const float4*)&Vs[j * V_STRIDE + tx * 8 + 4];
            const float vv[8] = {v0.x, v0.y, v0.z, v0.w, v1.x, v1.y, v1.z, v1.w};
#pragma unroll
            for (int i = 0; i < 4; i++) {
                const float pf = Ps[(ty * 4 + i) * QK_STRIDE + j];
#pragma unroll
                for (int c = 0; c < 8; c++) o[i][c] += pf * vv[c];
            }
        }
    }

    const int b = bh >> 4;
    const int h = bh & 15;
#pragma unroll
    for (int i = 0; i < 4; i++) {
        const float inv  = 1.0f / l_i[i];
        const int   srow = qbase + ty * 4 + i;
        float* dst = g_attn + (size_t)(b * SEQ + srow) * DMODEL + h * DKH + tx * 8;
        float r0[4], r1[4];
#pragma unroll
        for (int c = 0; c < 4; c++) { r0[c] = o[i][c] * inv; r1[c] = o[i][c + 4] * inv; }
        *(float4*)&dst[0] = *(float4*)r0;
        *(float4*)&dst[4] = *(float4*)r1;
    }
}

// ---------------------------------------------------------------------------
extern "C" void kernel_launch(void* const* d_in, const int* in_sizes, int n_in,
                              void* d_out, int out_size) {
    const float* x  = (const float*)d_in[0];
    const float* Wq = (const float*)d_in[1];
    const float* Wk = (const float*)d_in[2];
    const float* Wv = (const float*)d_in[3];
    const float* Wo = (const float*)d_in[4];
    const int* use_mask = (const int*)d_in[5];

    float *q, *k, *v, *attn;
    cudaGetSymbolAddress((void**)&q, g_q);
    cudaGetSymbolAddress((void**)&k, g_k);
    cudaGetSymbolAddress((void**)&v, g_v);
    cudaGetSymbolAddress((void**)&attn, g_attn);
    __nv_bfloat16 *xh, *xl, *wh, *wl;
    cudaGetSymbolAddress((void**)&xh, g_xh);
    cudaGetSymbolAddress((void**)&xl, g_xl);
    cudaGetSymbolAddress((void**)&wh, g_wh);
    cudaGetSymbolAddress((void**)&wl, g_wl);

    const int flash_smem = SMEM_FLOATS * (int)sizeof(float);
    cudaFuncSetAttribute(flash_attn, cudaFuncAttributeMaxDynamicSharedMemorySize, flash_smem);
    cudaFuncSetAttribute(gemm_mma<1>, cudaFuncAttributeMaxDynamicSharedMemorySize, GEMM_SMEM);
    cudaFuncSetAttribute(gemm_mma<0>, cudaFuncAttributeMaxDynamicSharedMemorySize, GEMM_SMEM);

    const int n4x = MROWS * DMODEL / 4;
    const int n4w = DMODEL * DMODEL / 4;
    const dim3 gg(DMODEL / 128, MROWS / 128);  // (16, 64)

    split_kernel<<<n4x / 256, 256>>>(x, xh, xl, n4x);

    split_kernel<<<n4w / 256, 256>>>(Wq, wh, wl, n4w);
    gemm_mma<1><<<gg, 256, GEMM_SMEM>>>(xh, xl, wh, wl, q);
    split_kernel<<<n4w / 256, 256>>>(Wk, wh, wl, n4w);
    gemm_mma<1><<<gg, 256, GEMM_SMEM>>>(xh, xl, wh, wl, k);
    split_kernel<<<n4w / 256, 256>>>(Wv, wh, wl, n4w);
    gemm_mma<1><<<gg, 256, GEMM_SMEM>>>(xh, xl, wh, wl, v);

    flash_attn<<<dim3(SEQ / 64, BATCH * NH), 256, flash_smem>>>(use_mask);

    split_kernel<<<n4x / 256, 256>>>(attn, xh, xl, n4x);
    split_kernel<<<n4w / 256, 256>>>(Wo, wh, wl, n4w);
    gemm_mma<0><<<gg, 256, GEMM_SMEM>>>(xh, xl, wh, wl, (float*)d_out);
}